// round 15
// baseline (speedup 1.0000x reference)
#include <cuda_runtime.h>
#include <math.h>
#include <stdint.h>

#define NB 32
#define NC 256
#define NK 64
#define NHW 4096
#define NIN 320
#define BN_EPS 1e-5f
typedef unsigned short ush;

// -------- scratch offsets (floats; all multiples of 4 -> 16B aligned) --------
#define OFF_CORR   0L
#define OFF_DW     8388608L
#define OFF_S      50331648L
#define OFF_PX     83886080L
#define OFF_G      117440512L
#define OFF_T1     119537664L
#define OFF_ATT    121634816L
#define OFF_T2     123731968L
#define OFF_M      125829120L
#define OFF_R      127926272L
#define OFF_U      127934464L
#define OFF_W2     127942656L
#define OFF_CV     127950848L
#define OFF_ZT_H   127959040L
#define OFF_ZT_L   128221184L
#define OFF_XT_H   128483328L
#define OFF_XT_L   145260544L
#define OFF_DWT_H  162037760L
#define OFF_DWT_L  183009280L
#define OFF_ST_H   203980800L
#define OFF_ST_L   220758016L
#define OFF_PXP_H  237535232L
#define OFF_PXP_L  254312448L
#define OFF_PXT_H  271089664L
#define OFF_PXT_L  287866880L
#define OFF_PWW_H  304644096L
#define OFF_PWW_L  304685056L
#define OFF_INW_H  304726016L
#define OFF_INW_L  304758784L
#define OFF_MMP_H  304791552L
#define OFF_MMP_L  305840128L
#define SCRATCH_FLOATS 306888704L
__device__ float g_scratch[SCRATCH_FLOATS];

// ------------------------------ helpers --------------------------------------
__device__ __forceinline__ uint32_t smem_u32(const void* p) {
    uint32_t a;
    asm("{ .reg .u64 t; cvta.to.shared.u64 t, %1; cvt.u32.u64 %0, t; }" : "=r"(a) : "l"(p));
    return a;
}
__device__ __forceinline__ void split2(float f, ush& h, ush& l) {
    uint32_t u = __float_as_uint(f);
    uint32_t hb = (u + 0x7fffu + ((u >> 16) & 1u)) >> 16;
    float hf = __uint_as_float(hb << 16);
    float r = f - hf;
    uint32_t u2 = __float_as_uint(r);
    uint32_t lb = (u2 + 0x7fffu + ((u2 >> 16) & 1u)) >> 16;
    h = (ush)hb; l = (ush)lb;
}
__device__ __forceinline__ void ldsm4(uint32_t* a, uint32_t addr) {
    asm volatile("ldmatrix.sync.aligned.m8n8.x4.shared.b16 {%0,%1,%2,%3}, [%4];"
        : "=r"(a[0]), "=r"(a[1]), "=r"(a[2]), "=r"(a[3]) : "r"(addr));
}
__device__ __forceinline__ void mma16816(float* c, const uint32_t* a, const uint32_t* b) {
    asm volatile("mma.sync.aligned.m16n8k16.row.col.f32.bf16.bf16.f32 "
        "{%0,%1,%2,%3}, {%4,%5,%6,%7}, {%8,%9}, {%0,%1,%2,%3};"
        : "+f"(c[0]), "+f"(c[1]), "+f"(c[2]), "+f"(c[3])
        : "r"(a[0]), "r"(a[1]), "r"(a[2]), "r"(a[3]), "r"(b[0]), "r"(b[1]));
}
__device__ __forceinline__ void cpasync16(uint32_t dst, const void* src) {
    asm volatile("cp.async.cg.shared.global [%0], [%1], 16;"
        :: "r"(dst), "l"(src) : "memory");
}

#define PITCH 40          // ush per smem row
#define STAGE_BYTES 40960 // A_H|A_L|B_H|B_L, each 128*40*2 = 10240 B
#define MG2_SMEM 81920

// =============================================================================
// bf16-pair GEMM, cp.async double-buffered, 2 CTAs/SM.
// C[b](M,N) = A[b](M,K) @ B[b](N,K)^T ; A,B bf16 hi/lo pairs, K-major.
// EPI: 0 plain | 1 +bias, emit CP pairs + CT transposed pairs
//      2 bias+BN+ReLU, emit CT transposed pairs | 4 +e0[b,m]+e1[b,m,n]
// SPLIT>1: atomicAdd epilogue (C pre-zeroed), EPI must be 0.
// =============================================================================
template<int EPI, int SPLIT>
__global__ __launch_bounds__(256, 2) void mg2_k(
    const ush* __restrict__ Ah, const ush* __restrict__ Al, long aBS, int Mtot,
    const ush* __restrict__ Bh, const ush* __restrict__ Bl, long bBS,
    float* __restrict__ C, long cBS, int Npitch, int Ktot,
    const float* __restrict__ e0, const float* __restrict__ e1,
    const float* __restrict__ e2, const float* __restrict__ e3,
    const float* __restrict__ e4,
    ush* __restrict__ CPh, ush* __restrict__ CPl,
    ush* __restrict__ CTh, ush* __restrict__ CTl, int Mdim)
{
    extern __shared__ char dynsm[];
    const int t = threadIdx.x, lane = t & 31, w = t >> 5;
    const int b  = blockIdx.z / SPLIT;
    const int ks = blockIdx.z % SPLIT;
    const int m0 = blockIdx.y * 128, n0 = blockIdx.x * 128;
    const int wm = (w & 1) * 64, wn = (w >> 1) * 32;
    const ush* Ahb = Ah + (long)b * aBS;
    const ush* Alb = Al + (long)b * aBS;
    const ush* Bhb = Bh + (long)b * bBS;
    const ush* Blb = Bl + (long)b * bBS;
    const int Kc = Ktot / SPLIT;
    const int kbeg = ks * Kc;
    const int nch = Kc / 32;
    const uint32_t smb = smem_u32(dynsm);

    float acc[4][4][4];
    #pragma unroll
    for (int i = 0; i < 4; i++)
        #pragma unroll
        for (int j = 0; j < 4; j++)
            #pragma unroll
            for (int q = 0; q < 4; q++) acc[i][j][q] = 0.0f;

    auto issue = [&](int c, int buf) {
        const int k0 = kbeg + c * 32;
        const uint32_t sb = smb + buf * STAGE_BYTES;
        #pragma unroll
        for (int i = 0; i < 2; i++) {
            int id = t + i * 256;
            int row = id >> 2, seg = id & 3;
            uint32_t d = (uint32_t)(row * (PITCH * 2) + seg * 16);
            int ar = m0 + row; if (ar >= Mtot) ar = Mtot - 1;
            cpasync16(sb + d,         Ahb + (long)ar * Ktot + k0 + seg * 8);
            cpasync16(sb + 10240 + d, Alb + (long)ar * Ktot + k0 + seg * 8);
            long br = (long)(n0 + row);
            cpasync16(sb + 20480 + d, Bhb + br * Ktot + k0 + seg * 8);
            cpasync16(sb + 30720 + d, Blb + br * Ktot + k0 + seg * 8);
        }
        asm volatile("cp.async.commit_group;" ::: "memory");
    };

    issue(0, 0);
    for (int c = 0; c < nch; c++) {
        if (c + 1 < nch) {
            issue(c + 1, (c + 1) & 1);
            asm volatile("cp.async.wait_group 1;" ::: "memory");
        } else {
            asm volatile("cp.async.wait_group 0;" ::: "memory");
        }
        __syncthreads();
        const uint32_t sb = smb + (c & 1) * STAGE_BYTES;
        const uint32_t aH = sb, aL = sb + 10240, bH = sb + 20480, bL = sb + 30720;
        #pragma unroll
        for (int s = 0; s < 2; s++) {
            const int kk = s * 16;
            // B fragments: two n-tiles per ldmatrix.x4 (halves LDSM issue count)
            uint32_t fBH[4][2], fBL[4][2];
            #pragma unroll
            for (int np2 = 0; np2 < 2; np2++) {
                int row = wn + np2 * 16 + (lane & 7) + ((lane >> 4) << 3);
                int col = kk + (((lane >> 3) & 1) << 3);
                uint32_t off = (uint32_t)(row * PITCH + col) * 2u;
                uint32_t rh[4], rl[4];
                ldsm4(rh, bH + off);
                ldsm4(rl, bL + off);
                fBH[np2 * 2][0] = rh[0]; fBH[np2 * 2][1] = rh[1];
                fBH[np2 * 2 + 1][0] = rh[2]; fBH[np2 * 2 + 1][1] = rh[3];
                fBL[np2 * 2][0] = rl[0]; fBL[np2 * 2][1] = rl[1];
                fBL[np2 * 2 + 1][0] = rl[2]; fBL[np2 * 2 + 1][1] = rl[3];
            }
            #pragma unroll
            for (int mt = 0; mt < 4; mt++) {
                int row = wm + mt * 16 + (lane & 15);
                int col = kk + (lane >> 4) * 8;
                uint32_t off = (uint32_t)(row * PITCH + col) * 2u;
                uint32_t fAH[4], fAL[4];
                ldsm4(fAH, aH + off);
                ldsm4(fAL, aL + off);
                #pragma unroll
                for (int nt = 0; nt < 4; nt++) {
                    mma16816(acc[mt][nt], fAH, fBH[nt]);
                    mma16816(acc[mt][nt], fAL, fBH[nt]);
                    mma16816(acc[mt][nt], fAH, fBL[nt]);
                }
            }
        }
        __syncthreads();
    }

    // ---------------- epilogue ----------------
    float* tsm = reinterpret_cast<float*>(dynsm);   // reuse pipeline smem: [128][132]
    #pragma unroll
    for (int mt = 0; mt < 4; mt++) {
        #pragma unroll
        for (int half = 0; half < 2; half++) {
            const int ml = wm + mt * 16 + (lane >> 2) + half * 8;
            const int m = m0 + ml;
            if (m >= Mtot) continue;
            float bias = 0.f, mean = 0.f, scale = 1.f, beta = 0.f, cv = 0.f;
            if (EPI == 1) bias = e0[m];
            if (EPI == 2) {
                bias = e0[m]; mean = e1[m];
                scale = rsqrtf(e2[m] + BN_EPS) * e3[m]; beta = e4[m];
            }
            if (EPI == 4) cv = e0[b * NC + m];
            #pragma unroll
            for (int nt = 0; nt < 4; nt++) {
                const int nl = wn + nt * 8 + (lane & 3) * 2;
                const int n = n0 + nl;
                float v0 = acc[mt][nt][half * 2 + 0];
                float v1 = acc[mt][nt][half * 2 + 1];
                if (SPLIT > 1) {
                    atomicAdd(&C[(long)b * cBS + (long)m * Npitch + n], v0);
                    atomicAdd(&C[(long)b * cBS + (long)m * Npitch + n + 1], v1);
                    continue;
                }
                if (EPI == 1) { v0 += bias; v1 += bias; }
                else if (EPI == 2) {
                    v0 = fmaxf((v0 + bias - mean) * scale + beta, 0.f);
                    v1 = fmaxf((v1 + bias - mean) * scale + beta, 0.f);
                } else if (EPI == 4) {
                    const float* sr = e1 + (long)b * cBS + (long)m * Npitch + n;
                    v0 += cv + sr[0]; v1 += cv + sr[1];
                }
                *reinterpret_cast<float2*>(&C[(long)b * cBS + (long)m * Npitch + n]) =
                    make_float2(v0, v1);
                if (EPI == 1) {      // straight pairs (same layout as C)
                    ush h0, l0, h1, l1;
                    split2(v0, h0, l0); split2(v1, h1, l1);
                    *reinterpret_cast<uint32_t*>(&CPh[(long)b * cBS + (long)m * Npitch + n]) =
                        (uint32_t)h0 | ((uint32_t)h1 << 16);
                    *reinterpret_cast<uint32_t*>(&CPl[(long)b * cBS + (long)m * Npitch + n]) =
                        (uint32_t)l0 | ((uint32_t)l1 << 16);
                }
                if (EPI == 1 || EPI == 2) {
                    tsm[ml * 132 + nl] = v0;
                    tsm[ml * 132 + nl + 1] = v1;
                }
            }
        }
    }
    if (EPI == 1 || EPI == 2) {      // transposed pairs via smem
        __syncthreads();
        const int nl = t >> 1, mseg = (t & 1) * 64;
        ush* dh = CTh + ((long)b * NHW + n0 + nl) * Mdim + m0 + mseg;
        ush* dl = CTl + ((long)b * NHW + n0 + nl) * Mdim + m0 + mseg;
        #pragma unroll
        for (int j = 0; j < 64; j += 8) {
            uint32_t hw[4], lw[4];
            #pragma unroll
            for (int p = 0; p < 4; p++) {
                float f0 = tsm[(mseg + j + 2 * p) * 132 + nl];
                float f1 = tsm[(mseg + j + 2 * p + 1) * 132 + nl];
                ush h0, l0, h1, l1;
                split2(f0, h0, l0); split2(f1, h1, l1);
                hw[p] = (uint32_t)h0 | ((uint32_t)h1 << 16);
                lw[p] = (uint32_t)l0 | ((uint32_t)l1 << 16);
            }
            *reinterpret_cast<uint4*>(dh + j) = make_uint4(hw[0], hw[1], hw[2], hw[3]);
            *reinterpret_cast<uint4*>(dl + j) = make_uint4(lw[0], lw[1], lw[2], lw[3]);
        }
    }
}

__global__ void zero_k(float* __restrict__ p, long n)
{
    long i = (long)blockIdx.x * blockDim.x + threadIdx.x;
    if (i < n) p[i] = 0.0f;
}

// fused weight conversion: two fp32 tensors -> bf16 hi/lo pairs in one launch
__global__ __launch_bounds__(256) void convP2_k(
    const float* __restrict__ a, long na, ush* __restrict__ ah, ush* __restrict__ al,
    const float* __restrict__ bb, long nb2, ush* __restrict__ bh, ush* __restrict__ bl)
{
    long i = (long)blockIdx.x * 256 + threadIdx.x;
    if (i < na) {
        ush h, l;
        split2(a[i], h, l);
        ah[i] = h; al[i] = l;
    } else if (i < na + nb2) {
        long j = i - na;
        ush h, l;
        split2(bb[j], h, l);
        bh[j] = h; bl[j] = l;
    }
}

// transpose-convert: in [b][R][Cc] fp32 -> out pairs [b][Cc][R]
__global__ __launch_bounds__(256) void convT_k(const float* __restrict__ in,
    ush* __restrict__ oh, ush* __restrict__ ol, int R, int Cc)
{
    __shared__ float tsm[32][33];
    const int b = blockIdx.z, c0 = blockIdx.x * 32, r0 = blockIdx.y * 32;
    const int lane = threadIdx.x & 31, wy = threadIdx.x >> 5;
    const float* src = in + ((long)b * R + r0) * Cc + c0;
    #pragma unroll
    for (int p = 0; p < 4; p++) {
        int r = wy + p * 8;
        tsm[r][lane] = src[(long)r * Cc + lane];
    }
    __syncthreads();
    ush* dh = oh + ((long)b * Cc + c0) * R + r0;
    ush* dl = ol + ((long)b * Cc + c0) * R + r0;
    #pragma unroll
    for (int p = 0; p < 4; p++) {
        int cc = wy + p * 8;
        float v = tsm[lane][cc];
        ush h, l;
        split2(v, h, l);
        dh[(long)cc * R + lane] = h;
        dl[(long)cc * R + lane] = l;
    }
}

// fused transpose-convert for x (blocks 0..127) and z (blocks 128..129); R = NC
__global__ __launch_bounds__(256) void convTX_k(
    const float* __restrict__ xin, ush* __restrict__ xh, ush* __restrict__ xl,
    const float* __restrict__ zin, ush* __restrict__ zh, ush* __restrict__ zl)
{
    __shared__ float tsm[32][33];
    const int b = blockIdx.z, bx = blockIdx.x;
    const float* in; ush* oh; ush* ol; int Cc, c0;
    if (bx < 128) { in = xin; oh = xh; ol = xl; Cc = NHW; c0 = bx * 32; }
    else          { in = zin; oh = zh; ol = zl; Cc = NK;  c0 = (bx - 128) * 32; }
    const int r0 = blockIdx.y * 32;
    const int lane = threadIdx.x & 31, wy = threadIdx.x >> 5;
    const float* src = in + ((long)b * NC + r0) * Cc + c0;
    #pragma unroll
    for (int p = 0; p < 4; p++) {
        int r = wy + p * 8;
        tsm[r][lane] = src[(long)r * Cc + lane];
    }
    __syncthreads();
    ush* dh = oh + ((long)b * Cc + c0) * NC + r0;
    ush* dl = ol + ((long)b * Cc + c0) * NC + r0;
    #pragma unroll
    for (int p = 0; p < 4; p++) {
        int cc = wy + p * 8;
        float v = tsm[lane][cc];
        ush h, l;
        split2(v, h, l);
        dh[(long)cc * NC + lane] = h;
        dl[(long)cc * NC + lane] = l;
    }
}

// ------------------ depthwise 3x3: division-free staging + row-pair compute ---
// Each thread computes 2 consecutive rows x 8 cols in one pass (16 outputs).
__global__ __launch_bounds__(256) void dw_k(
    const float* __restrict__ corr, const float* __restrict__ dten,
    const float* __restrict__ w, const float* __restrict__ bias, float* __restrict__ out)
{
    const int bc = blockIdx.x;
    const int b = bc / NIN, ch = bc % NIN;
    const float* src = (ch < NK) ? (corr + ((long)b * NK + ch) * NHW)
                                 : (dten + ((long)b * NC + (ch - NK)) * NHW);
    __shared__ float tile[66][66];
    const int t = threadIdx.x;
    const int wid = t >> 5, lane = t & 31;

    // division-free halo staging: warp per row, lanes stride columns
    for (int row = wid; row < 66; row += 8) {
        const int gy = row - 1;
        float* trow = tile[row];
        if (gy >= 0 && gy < 64) {
            const float* srow = src + gy * 64;
            for (int col = lane; col < 66; col += 32) {
                int gx = col - 1;
                trow[col] = (gx >= 0 && gx < 64) ? srow[gx] : 0.0f;
            }
        } else {
            for (int col = lane; col < 66; col += 32) trow[col] = 0.0f;
        }
    }
    __syncthreads();

    float wk[9];
    #pragma unroll
    for (int i = 0; i < 9; i++) wk[i] = w[ch * 9 + i];
    const float bb = bias[ch];

    // compute: thread -> rows (2*tr, 2*tr+1), cols seg..seg+7
    const int seg = (t & 7) * 8;      // 0..56
    const int tr  = t >> 3;           // 0..31
    const int y   = tr * 2;           // 0..62
    float rv[4][10];
    #pragma unroll
    for (int ky = 0; ky < 4; ky++) {
        const float* trp = &tile[y + ky][seg];
        #pragma unroll
        for (int i = 0; i < 10; i++) rv[ky][i] = trp[i];
    }
    float o0[8], o1[8];
    #pragma unroll
    for (int j = 0; j < 8; j++) {
        float a0 = bb, a1 = bb;
        #pragma unroll
        for (int kx = 0; kx < 3; kx++) {
            a0 = fmaf(wk[0 * 3 + kx], rv[0][j + kx], a0);
            a0 = fmaf(wk[1 * 3 + kx], rv[1][j + kx], a0);
            a0 = fmaf(wk[2 * 3 + kx], rv[2][j + kx], a0);
            a1 = fmaf(wk[0 * 3 + kx], rv[1][j + kx], a1);
            a1 = fmaf(wk[1 * 3 + kx], rv[2][j + kx], a1);
            a1 = fmaf(wk[2 * 3 + kx], rv[3][j + kx], a1);
        }
        o0[j] = a0; o1[j] = a1;
    }
    float* dst = out + (long)bc * NHW + y * 64 + seg;
    *reinterpret_cast<float4*>(dst)          = make_float4(o0[0], o0[1], o0[2], o0[3]);
    *reinterpret_cast<float4*>(dst + 4)      = make_float4(o0[4], o0[5], o0[6], o0[7]);
    *reinterpret_cast<float4*>(dst + 64)     = make_float4(o1[0], o1[1], o1[2], o1[3]);
    *reinterpret_cast<float4*>(dst + 68)     = make_float4(o1[4], o1[5], o1[6], o1[7]);
}

__global__ __launch_bounds__(256) void rowsum_k(const float* __restrict__ px, float* __restrict__ r)
{
    int row = blockIdx.x * 8 + (threadIdx.x >> 5), lane = threadIdx.x & 31;
    const float* p = px + (long)row * NHW;
    float s = 0.0f;
    for (int i = lane; i < NHW; i += 32) s += p[i];
    #pragma unroll
    for (int o = 16; o; o >>= 1) s += __shfl_xor_sync(0xffffffffu, s, o);
    if (lane == 0) r[row] = s;
}

__global__ __launch_bounds__(256) void uw_k(
    const float* __restrict__ Wq, const float* __restrict__ Wk,
    const float* __restrict__ r, float* __restrict__ u, float* __restrict__ w)
{
    int b = blockIdx.x, t = threadIdx.x;
    __shared__ float rs[NC];
    rs[t] = r[b * NC + t];
    __syncthreads();
    float uu = 0.0f, ww = 0.0f;
    for (int c = 0; c < NC; c++) {
        float rc = rs[c];
        uu = fmaf(Wq[t * NC + c], rc, uu);
        ww = fmaf(Wk[t * NC + c], rc, ww);
    }
    u[b * NC + t] = uu;
    w[b * NC + t] = ww;
}

__global__ __launch_bounds__(256) void softmax_k(float* __restrict__ s)
{
    float* p = s + (long)blockIdx.x * NC;
    int t = threadIdx.x, lane = t & 31, wp = t >> 5;
    __shared__ float redm[8], reds[8];
    __shared__ float bm, bs;
    float v = p[t];
    float m = v;
    #pragma unroll
    for (int o = 16; o; o >>= 1) m = fmaxf(m, __shfl_xor_sync(0xffffffffu, m, o));
    if (lane == 0) redm[wp] = m;
    __syncthreads();
    if (t == 0) {
        float mm = redm[0];
        for (int i = 1; i < 8; i++) mm = fmaxf(mm, redm[i]);
        bm = mm;
    }
    __syncthreads();
    float e = expf(v - bm);
    float su = e;
    #pragma unroll
    for (int o = 16; o; o >>= 1) su += __shfl_xor_sync(0xffffffffu, su, o);
    if (lane == 0) reds[wp] = su;
    __syncthreads();
    if (t == 0) {
        float ss = 0.0f;
        for (int i = 0; i < 8; i++) ss += reds[i];
        bs = 1.0f / ss;
    }
    __syncthreads();
    p[t] = e * bs;
}

__global__ __launch_bounds__(256) void ycvec_k(
    const float* __restrict__ att, const float* __restrict__ bv,
    const float* __restrict__ Wo, const float* __restrict__ ob, float* __restrict__ cvec)
{
    int b = blockIdx.x, t = threadIdx.x;
    __shared__ float ys[NC];
    const float* ab = att + (long)b * NC * NC;
    float y = 0.0f;
    for (int c = 0; c < NC; c++) y = fmaf(ab[c * NC + t], bv[c], y);
    ys[t] = y;
    __syncthreads();
    float cv = 0.0f;
    for (int d = 0; d < NC; d++) cv = fmaf(Wo[t * NC + d], ys[d], cv);
    cvec[b * NC + t] = cv + ob[t];
}

// ------------- small scalar GEMM (64x64 tile, 4x4/thread) ---------------------
// EPI: 0 none | 3 score epilogue | 5 plain store + emit bf16 pairs (oh/ol)
template<int AM, int BM, int EPI>
__global__ __launch_bounds__(256) void gemm_k(
    const float* __restrict__ A, const float* __restrict__ Bm, float* __restrict__ Cm,
    int M, int N, int Kd, long aBS, long bBS, long cBS,
    const float* __restrict__ p0, const float* __restrict__ p1,
    const float* __restrict__ p2, const float* __restrict__ p3,
    ush* __restrict__ oh, ush* __restrict__ ol)
{
    __shared__ float As[16][64];
    __shared__ float Bs[16][64];
    const int b = blockIdx.z;
    const float* Ab = A + (long)b * aBS;
    const float* Bb = Bm + (long)b * bBS;
    float* Cb = Cm + (long)b * cBS;
    const int n0 = blockIdx.x * 64, m0 = blockIdx.y * 64;
    const int t = threadIdx.x, tx = t & 15, ty = t >> 4;
    float acc[4][4] = {};
    for (int k0 = 0; k0 < Kd; k0 += 16) {
        if (AM == 0) {
            int m = t >> 2, kq = (t & 3) * 4;
            float4 va = *reinterpret_cast<const float4*>(&Ab[(long)(m0 + m) * Kd + k0 + kq]);
            As[kq + 0][m] = va.x; As[kq + 1][m] = va.y;
            As[kq + 2][m] = va.z; As[kq + 3][m] = va.w;
        } else {
            int kk = t >> 4, mq = (t & 15) * 4;
            float4 va = *reinterpret_cast<const float4*>(&Ab[(long)(k0 + kk) * M + m0 + mq]);
            *reinterpret_cast<float4*>(&As[kk][mq]) = va;
        }
        if (BM == 0) {
            int kk = t >> 4, nq = (t & 15) * 4;
            float4 vb = *reinterpret_cast<const float4*>(&Bb[(long)(k0 + kk) * N + n0 + nq]);
            *reinterpret_cast<float4*>(&Bs[kk][nq]) = vb;
        } else {
            int n = t >> 2, kq = (t & 3) * 4;
            float4 vb = *reinterpret_cast<const float4*>(&Bb[(long)(n0 + n) * Kd + k0 + kq]);
            Bs[kq + 0][n] = vb.x; Bs[kq + 1][n] = vb.y;
            Bs[kq + 2][n] = vb.z; Bs[kq + 3][n] = vb.w;
        }
        __syncthreads();
        #pragma unroll
        for (int kk = 0; kk < 16; kk++) {
            float4 af = *reinterpret_cast<const float4*>(&As[kk][ty * 4]);
            float4 bf = *reinterpret_cast<const float4*>(&Bs[kk][tx * 4]);
            float a[4] = {af.x, af.y, af.z, af.w};
            float bb[4] = {bf.x, bf.y, bf.z, bf.w};
            #pragma unroll
            for (int i = 0; i < 4; i++)
                #pragma unroll
                for (int j = 0; j < 4; j++)
                    acc[i][j] = fmaf(a[i], bb[j], acc[i][j]);
        }
        __syncthreads();
    }
    #pragma unroll
    for (int i = 0; i < 4; i++) {
        int m = m0 + ty * 4 + i;
        float vv[4];
        #pragma unroll
        for (int j = 0; j < 4; j++) {
            int n = n0 + tx * 4 + j;
            float x = acc[i][j];
            if (EPI == 3) {
                float u = p0[b * NC + m], bk = p1[n], bq = p2[m], w = p3[b * NC + n];
                x = (x + u * bk + bq * w + 4096.0f * bq * bk) * 0.0625f;
            }
            vv[j] = x;
        }
        *reinterpret_cast<float4*>(&Cb[(long)m * N + n0 + tx * 4]) =
            make_float4(vv[0], vv[1], vv[2], vv[3]);
        if (EPI == 5) {
            uint32_t hw[2], lw[2];
            #pragma unroll
            for (int p = 0; p < 2; p++) {
                ush h0, l0, h1, l1;
                split2(vv[2 * p], h0, l0);
                split2(vv[2 * p + 1], h1, l1);
                hw[p] = (uint32_t)h0 | ((uint32_t)h1 << 16);
                lw[p] = (uint32_t)l0 | ((uint32_t)l1 << 16);
            }
            *reinterpret_cast<uint2*>(&oh[(long)b * cBS + (long)m * N + n0 + tx * 4]) =
                make_uint2(hw[0], hw[1]);
            *reinterpret_cast<uint2*>(&ol[(long)b * cBS + (long)m * N + n0 + tx * 4]) =
                make_uint2(lw[0], lw[1]);
        }
    }
}

// =============================================================================
extern "C" void kernel_launch(void* const* d_in, const int* in_sizes, int n_in,
                              void* d_out, int out_size)
{
    const float* z     = (const float*)d_in[0];
    const float* x     = (const float*)d_in[1];
    const float* dten  = (const float*)d_in[2];
    const float* dw_w  = (const float*)d_in[3];
    const float* dw_b  = (const float*)d_in[4];
    const float* pw_w  = (const float*)d_in[5];
    const float* pw_b  = (const float*)d_in[6];
    const float* bn_g  = (const float*)d_in[7];
    const float* bn_be = (const float*)d_in[8];
    const float* bn_m  = (const float*)d_in[9];
    const float* bn_v  = (const float*)d_in[10];
    const float* inp_w = (const float*)d_in[11];
    const float* inp_b = (const float*)d_in[12];
    const float* q_w   = (const float*)d_in[13];
    const float* q_b   = (const float*)d_in[14];
    const float* k_w   = (const float*)d_in[15];
    const float* k_b   = (const float*)d_in[16];
    const float* v_w   = (const float*)d_in[17];
    const float* v_b   = (const float*)d_in[18];
    const float* op_w  = (const float*)d_in[19];
    const float* op_b  = (const float*)d_in[20];
    float* out = (float*)d_out;

    float* base = nullptr;
    cudaGetSymbolAddress((void**)&base, g_scratch);
    float* corr = base + OFF_CORR;
    float* dwb  = base + OFF_DW;
    float* sbuf = base + OFF_S;
    float* px   = base + OFF_PX;
    float* G    = base + OFF_G;
    float* T1   = base + OFF_T1;
    float* att  = base + OFF_ATT;
    float* T2   = base + OFF_T2;
    float* Mm   = base + OFF_M;
    float* r    = base + OFF_R;
    float* u    = base + OFF_U;
    float* w    = base + OFF_W2;
    float* cvec = base + OFF_CV;
    ush* ztH  = (ush*)(base + OFF_ZT_H);  ush* ztL  = (ush*)(base + OFF_ZT_L);
    ush* xtH  = (ush*)(base + OFF_XT_H);  ush* xtL  = (ush*)(base + OFF_XT_L);
    ush* dwtH = (ush*)(base + OFF_DWT_H); ush* dwtL = (ush*)(base + OFF_DWT_L);
    ush* stH  = (ush*)(base + OFF_ST_H);  ush* stL  = (ush*)(base + OFF_ST_L);
    ush* pxpH = (ush*)(base + OFF_PXP_H); ush* pxpL = (ush*)(base + OFF_PXP_L);
    ush* pxtH = (ush*)(base + OFF_PXT_H); ush* pxtL = (ush*)(base + OFF_PXT_L);
    ush* pwwH = (ush*)(base + OFF_PWW_H); ush* pwwL = (ush*)(base + OFF_PWW_L);
    ush* inwH = (ush*)(base + OFF_INW_H); ush* inwL = (ush*)(base + OFF_INW_L);
    ush* mmpH = (ush*)(base + OFF_MMP_H); ush* mmpL = (ush*)(base + OFF_MMP_L);

    cudaFuncSetAttribute(mg2_k<0,1>, cudaFuncAttributeMaxDynamicSharedMemorySize, MG2_SMEM);
    cudaFuncSetAttribute(mg2_k<1,1>, cudaFuncAttributeMaxDynamicSharedMemorySize, MG2_SMEM);
    cudaFuncSetAttribute(mg2_k<2,1>, cudaFuncAttributeMaxDynamicSharedMemorySize, MG2_SMEM);
    cudaFuncSetAttribute(mg2_k<4,1>, cudaFuncAttributeMaxDynamicSharedMemorySize, MG2_SMEM);
    cudaFuncSetAttribute(mg2_k<0,4>, cudaFuncAttributeMaxDynamicSharedMemorySize, MG2_SMEM);

    dim3 blk(256);
    const float* np = nullptr;
    ush* nu = nullptr;

    // 1) fused weight conversion (pw_w + inp_w)
    convP2_k<<<(int)(((long)NC*NIN + (long)NC*NC + 255) / 256), blk>>>(
        pw_w, (long)NC*NIN, pwwH, pwwL, inp_w, (long)NC*NC, inwH, inwL);

    // 2) fused transpose-convert (x + z)
    convTX_k<<<dim3(130, 8, NB), blk>>>(x, xtH, xtL, z, ztH, ztL);

    // 3) corr[b] (64x4096) = zT @ xT^T
    mg2_k<0,1><<<dim3(32, 1, NB), blk, MG2_SMEM>>>(
        ztH, ztL, (long)NK*NC, NK, xtH, xtL, (long)NHW*NC,
        corr, (long)NK*NHW, NHW, NC, np,np,np,np,np, nu,nu,nu,nu, 0);

    // 4) depthwise (division-free), 5) transpose-convert its output
    dw_k<<<NB*NIN, blk>>>(corr, dten, dw_w, dw_b, dwb);
    convT_k<<<dim3(128, 10, NB), blk>>>(dwb, dwtH, dwtL, NIN, NHW);

    // 6) s = ReLU(BN(pw_w @ dw + b));  epilogue also emits sT pairs
    mg2_k<2,1><<<dim3(32, 2, NB), blk, MG2_SMEM>>>(
        pwwH, pwwL, 0L, NC, dwtH, dwtL, (long)NHW*NIN,
        sbuf, (long)NC*NHW, NHW, NIN, pw_b, bn_m, bn_v, bn_g, bn_be,
        nu, nu, stH, stL, NC);

    // 7) px = inp_w @ s + b;  epilogue emits pxP (straight) + pxT (transposed)
    mg2_k<1,1><<<dim3(32, 2, NB), blk, MG2_SMEM>>>(
        inwH, inwL, 0L, NC, stH, stL, (long)NHW*NC,
        px, (long)NC*NHW, NHW, NC, inp_b, np,np,np,np,
        pxpH, pxpL, pxtH, pxtL, NC);

    // 8) r = px row sums
    rowsum_k<<<NB*NC/8, blk>>>(px, r);

    // 9) G[b] = px @ px^T  (split-K x4, atomicAdd)
    zero_k<<<(int)(((long)NB*NC*NC + 1023)/1024), 1024>>>(G, (long)NB*NC*NC);
    mg2_k<0,4><<<dim3(2, 2, NB*4), blk, MG2_SMEM>>>(
        pxpH, pxpL, (long)NC*NHW, NC, pxpH, pxpL, (long)NC*NHW,
        G, (long)NC*NC, NC, NHW, np,np,np,np,np, nu,nu,nu,nu, 0);

    // 10) small chain (scalar)
    uw_k<<<NB, blk>>>(q_w, k_w, r, u, w);
    gemm_k<0,0,0><<<dim3(4, 4, NB), blk>>>(q_w, G, T1, NC, NC, NC,
        0L, (long)NC*NC, (long)NC*NC, np, np, np, np, nu, nu);
    gemm_k<0,1,3><<<dim3(4, 4, NB), blk>>>(T1, k_w, att, NC, NC, NC,
        (long)NC*NC, 0L, (long)NC*NC, u, k_b, q_b, w, nu, nu);
    softmax_k<<<NB*NC, blk>>>(att);
    ycvec_k<<<NB, blk>>>(att, v_b, op_w, op_b, cvec);
    gemm_k<1,0,0><<<dim3(4, 4, NB), blk>>>(att, v_w, T2, NC, NC, NC,
        (long)NC*NC, 0L, (long)NC*NC, np, np, np, np, nu, nu);
    gemm_k<0,0,5><<<dim3(4, 4, NB), blk>>>(op_w, T2, Mm, NC, NC, NC,
        0L, (long)NC*NC, (long)NC*NC, np, np, np, np, mmpH, mmpL);

    // 11) out = Mm @ px + cvec + s
    mg2_k<4,1><<<dim3(32, 2, NB), blk, MG2_SMEM>>>(
        mmpH, mmpL, (long)NC*NC, NC, pxtH, pxtL, (long)NHW*NC,
        out, (long)NC*NHW, NHW, NC, cvec, sbuf, np,np,np, nu,nu,nu,nu, 0);
}

// round 17
// speedup vs baseline: 1.0346x; 1.0346x over previous
#include <cuda_runtime.h>
#include <math.h>
#include <stdint.h>

#define NB 32
#define NC 256
#define NK 64
#define NHW 4096
#define NIN 320
#define BN_EPS 1e-5f
typedef unsigned short ush;

// -------- scratch offsets (floats; all multiples of 4 -> 16B aligned) --------
#define OFF_CORR   0L
#define OFF_DW     8388608L
#define OFF_S      50331648L
#define OFF_PX     83886080L
#define OFF_G      117440512L
#define OFF_T1     119537664L
#define OFF_ATT    121634816L
#define OFF_T2     123731968L
#define OFF_M      125829120L
#define OFF_R      127926272L
#define OFF_U      127934464L
#define OFF_W2     127942656L
#define OFF_CV     127950848L
#define OFF_ZT_H   127959040L
#define OFF_ZT_L   128221184L
#define OFF_XT_H   128483328L
#define OFF_XT_L   145260544L
#define OFF_DWT_H  162037760L
#define OFF_DWT_L  183009280L
#define OFF_ST_H   203980800L
#define OFF_ST_L   220758016L
#define OFF_PXP_H  237535232L
#define OFF_PXP_L  254312448L
#define OFF_PXT_H  271089664L
#define OFF_PXT_L  287866880L
#define OFF_PWW_H  304644096L
#define OFF_PWW_L  304685056L
#define OFF_INW_H  304726016L
#define OFF_INW_L  304758784L
#define OFF_MMP_H  304791552L
#define OFF_MMP_L  305840128L
#define SCRATCH_FLOATS 306888704L
__device__ float g_scratch[SCRATCH_FLOATS];

// ------------------------------ helpers --------------------------------------
__device__ __forceinline__ uint32_t smem_u32(const void* p) {
    uint32_t a;
    asm("{ .reg .u64 t; cvta.to.shared.u64 t, %1; cvt.u32.u64 %0, t; }" : "=r"(a) : "l"(p));
    return a;
}
__device__ __forceinline__ void split2(float f, ush& h, ush& l) {
    uint32_t u = __float_as_uint(f);
    uint32_t hb = (u + 0x7fffu + ((u >> 16) & 1u)) >> 16;
    float hf = __uint_as_float(hb << 16);
    float r = f - hf;
    uint32_t u2 = __float_as_uint(r);
    uint32_t lb = (u2 + 0x7fffu + ((u2 >> 16) & 1u)) >> 16;
    h = (ush)hb; l = (ush)lb;
}
__device__ __forceinline__ void ldsm4(uint32_t* a, uint32_t addr) {
    asm volatile("ldmatrix.sync.aligned.m8n8.x4.shared.b16 {%0,%1,%2,%3}, [%4];"
        : "=r"(a[0]), "=r"(a[1]), "=r"(a[2]), "=r"(a[3]) : "r"(addr));
}
__device__ __forceinline__ void mma16816(float* c, const uint32_t* a, const uint32_t* b) {
    asm volatile("mma.sync.aligned.m16n8k16.row.col.f32.bf16.bf16.f32 "
        "{%0,%1,%2,%3}, {%4,%5,%6,%7}, {%8,%9}, {%0,%1,%2,%3};"
        : "+f"(c[0]), "+f"(c[1]), "+f"(c[2]), "+f"(c[3])
        : "r"(a[0]), "r"(a[1]), "r"(a[2]), "r"(a[3]), "r"(b[0]), "r"(b[1]));
}
__device__ __forceinline__ void cpasync16(uint32_t dst, const void* src) {
    asm volatile("cp.async.cg.shared.global [%0], [%1], 16;"
        :: "r"(dst), "l"(src) : "memory");
}

#define PITCH 40          // ush per smem row
#define STAGE_BYTES 40960 // A_H|A_L|B_H|B_L, each 128*40*2 = 10240 B
#define MG2_SMEM 81920

// =============================================================================
// bf16-pair GEMM, cp.async double-buffered, 2 CTAs/SM.
// C[b](M,N) = A[b](M,K) @ B[b](N,K)^T ; A,B bf16 hi/lo pairs, K-major.
// EPI: 0 plain | 1 +bias, NO fp32 store; emit CP pairs + CT pairs + rowsum->Raux
//      2 bias+BN+ReLU, emit CT transposed pairs | 4 +e0[b,m]+e1[b,m,n]
// SPLIT>1: atomicAdd epilogue (C pre-zeroed), EPI must be 0.
// =============================================================================
template<int EPI, int SPLIT>
__global__ __launch_bounds__(256, 2) void mg2_k(
    const ush* __restrict__ Ah, const ush* __restrict__ Al, long aBS, int Mtot,
    const ush* __restrict__ Bh, const ush* __restrict__ Bl, long bBS,
    float* __restrict__ C, long cBS, int Npitch, int Ktot,
    const float* __restrict__ e0, const float* __restrict__ e1,
    const float* __restrict__ e2, const float* __restrict__ e3,
    const float* __restrict__ e4,
    ush* __restrict__ CPh, ush* __restrict__ CPl,
    ush* __restrict__ CTh, ush* __restrict__ CTl, int Mdim,
    float* __restrict__ Raux)
{
    extern __shared__ char dynsm[];
    const int t = threadIdx.x, lane = t & 31, w = t >> 5;
    const int b  = blockIdx.z / SPLIT;
    const int ks = blockIdx.z % SPLIT;
    const int m0 = blockIdx.y * 128, n0 = blockIdx.x * 128;
    const int wm = (w & 1) * 64, wn = (w >> 1) * 32;
    const ush* Ahb = Ah + (long)b * aBS;
    const ush* Alb = Al + (long)b * aBS;
    const ush* Bhb = Bh + (long)b * bBS;
    const ush* Blb = Bl + (long)b * bBS;
    const int Kc = Ktot / SPLIT;
    const int kbeg = ks * Kc;
    const int nch = Kc / 32;
    const uint32_t smb = smem_u32(dynsm);

    float acc[4][4][4];
    #pragma unroll
    for (int i = 0; i < 4; i++)
        #pragma unroll
        for (int j = 0; j < 4; j++)
            #pragma unroll
            for (int q = 0; q < 4; q++) acc[i][j][q] = 0.0f;

    auto issue = [&](int c, int buf) {
        const int k0 = kbeg + c * 32;
        const uint32_t sb = smb + buf * STAGE_BYTES;
        #pragma unroll
        for (int i = 0; i < 2; i++) {
            int id = t + i * 256;
            int row = id >> 2, seg = id & 3;
            uint32_t d = (uint32_t)(row * (PITCH * 2) + seg * 16);
            int ar = m0 + row; if (ar >= Mtot) ar = Mtot - 1;
            cpasync16(sb + d,         Ahb + (long)ar * Ktot + k0 + seg * 8);
            cpasync16(sb + 10240 + d, Alb + (long)ar * Ktot + k0 + seg * 8);
            long br = (long)(n0 + row);
            cpasync16(sb + 20480 + d, Bhb + br * Ktot + k0 + seg * 8);
            cpasync16(sb + 30720 + d, Blb + br * Ktot + k0 + seg * 8);
        }
        asm volatile("cp.async.commit_group;" ::: "memory");
    };

    issue(0, 0);
    for (int c = 0; c < nch; c++) {
        if (c + 1 < nch) {
            issue(c + 1, (c + 1) & 1);
            asm volatile("cp.async.wait_group 1;" ::: "memory");
        } else {
            asm volatile("cp.async.wait_group 0;" ::: "memory");
        }
        __syncthreads();
        const uint32_t sb = smb + (c & 1) * STAGE_BYTES;
        const uint32_t aH = sb, aL = sb + 10240, bH = sb + 20480, bL = sb + 30720;
        #pragma unroll
        for (int s = 0; s < 2; s++) {
            const int kk = s * 16;
            uint32_t fBH[4][2], fBL[4][2];
            #pragma unroll
            for (int np2 = 0; np2 < 2; np2++) {
                int row = wn + np2 * 16 + (lane & 7) + ((lane >> 4) << 3);
                int col = kk + (((lane >> 3) & 1) << 3);
                uint32_t off = (uint32_t)(row * PITCH + col) * 2u;
                uint32_t rh[4], rl[4];
                ldsm4(rh, bH + off);
                ldsm4(rl, bL + off);
                fBH[np2 * 2][0] = rh[0]; fBH[np2 * 2][1] = rh[1];
                fBH[np2 * 2 + 1][0] = rh[2]; fBH[np2 * 2 + 1][1] = rh[3];
                fBL[np2 * 2][0] = rl[0]; fBL[np2 * 2][1] = rl[1];
                fBL[np2 * 2 + 1][0] = rl[2]; fBL[np2 * 2 + 1][1] = rl[3];
            }
            #pragma unroll
            for (int mt = 0; mt < 4; mt++) {
                int row = wm + mt * 16 + (lane & 15);
                int col = kk + (lane >> 4) * 8;
                uint32_t off = (uint32_t)(row * PITCH + col) * 2u;
                uint32_t fAH[4], fAL[4];
                ldsm4(fAH, aH + off);
                ldsm4(fAL, aL + off);
                #pragma unroll
                for (int nt = 0; nt < 4; nt++) {
                    mma16816(acc[mt][nt], fAH, fBH[nt]);
                    mma16816(acc[mt][nt], fAL, fBH[nt]);
                    mma16816(acc[mt][nt], fAH, fBL[nt]);
                }
            }
        }
        __syncthreads();
    }

    // ---------------- epilogue ----------------
    float* tsm = reinterpret_cast<float*>(dynsm);   // reuse pipeline smem: [128][132]
    #pragma unroll
    for (int mt = 0; mt < 4; mt++) {
        #pragma unroll
        for (int half = 0; half < 2; half++) {
            const int ml = wm + mt * 16 + (lane >> 2) + half * 8;
            const int m = m0 + ml;
            if (m >= Mtot) continue;
            float bias = 0.f, mean = 0.f, scale = 1.f, beta = 0.f, cv = 0.f;
            if (EPI == 1) bias = e0[m];
            if (EPI == 2) {
                bias = e0[m]; mean = e1[m];
                scale = rsqrtf(e2[m] + BN_EPS) * e3[m]; beta = e4[m];
            }
            if (EPI == 4) cv = e0[b * NC + m];
            float rowp = 0.f;
            #pragma unroll
            for (int nt = 0; nt < 4; nt++) {
                const int nl = wn + nt * 8 + (lane & 3) * 2;
                const int n = n0 + nl;
                float v0 = acc[mt][nt][half * 2 + 0];
                float v1 = acc[mt][nt][half * 2 + 1];
                if (SPLIT > 1) {
                    atomicAdd(&C[(long)b * cBS + (long)m * Npitch + n], v0);
                    atomicAdd(&C[(long)b * cBS + (long)m * Npitch + n + 1], v1);
                    continue;
                }
                if (EPI == 1) {
                    v0 += bias; v1 += bias;
                    rowp += v0 + v1;
                    ush h0, l0, h1, l1;
                    split2(v0, h0, l0); split2(v1, h1, l1);
                    *reinterpret_cast<uint32_t*>(&CPh[(long)b * cBS + (long)m * Npitch + n]) =
                        (uint32_t)h0 | ((uint32_t)h1 << 16);
                    *reinterpret_cast<uint32_t*>(&CPl[(long)b * cBS + (long)m * Npitch + n]) =
                        (uint32_t)l0 | ((uint32_t)l1 << 16);
                } else if (EPI == 2) {
                    v0 = fmaxf((v0 + bias - mean) * scale + beta, 0.f);
                    v1 = fmaxf((v1 + bias - mean) * scale + beta, 0.f);
                    *reinterpret_cast<float2*>(&C[(long)b * cBS + (long)m * Npitch + n]) =
                        make_float2(v0, v1);
                } else if (EPI == 4) {
                    const float* sr = e1 + (long)b * cBS + (long)m * Npitch + n;
                    v0 += cv + sr[0]; v1 += cv + sr[1];
                    *reinterpret_cast<float2*>(&C[(long)b * cBS + (long)m * Npitch + n]) =
                        make_float2(v0, v1);
                } else {
                    *reinterpret_cast<float2*>(&C[(long)b * cBS + (long)m * Npitch + n]) =
                        make_float2(v0, v1);
                }
                if (EPI == 1 || EPI == 2) {
                    tsm[ml * 132 + nl] = v0;
                    tsm[ml * 132 + nl + 1] = v1;
                }
            }
            if (EPI == 1) {   // reduce the 4 lanes sharing this m, then one atomic
                rowp += __shfl_xor_sync(0xffffffffu, rowp, 1);
                rowp += __shfl_xor_sync(0xffffffffu, rowp, 2);
                if ((lane & 3) == 0) atomicAdd(&Raux[b * NC + m], rowp);
            }
        }
    }
    if (EPI == 1 || EPI == 2) {      // transposed pairs via smem
        __syncthreads();
        const int nl = t >> 1, mseg = (t & 1) * 64;
        ush* dh = CTh + ((long)b * NHW + n0 + nl) * Mdim + m0 + mseg;
        ush* dl = CTl + ((long)b * NHW + n0 + nl) * Mdim + m0 + mseg;
        #pragma unroll
        for (int j = 0; j < 64; j += 8) {
            uint32_t hw[4], lw[4];
            #pragma unroll
            for (int p = 0; p < 4; p++) {
                float f0 = tsm[(mseg + j + 2 * p) * 132 + nl];
                float f1 = tsm[(mseg + j + 2 * p + 1) * 132 + nl];
                ush h0, l0, h1, l1;
                split2(f0, h0, l0); split2(f1, h1, l1);
                hw[p] = (uint32_t)h0 | ((uint32_t)h1 << 16);
                lw[p] = (uint32_t)l0 | ((uint32_t)l1 << 16);
            }
            *reinterpret_cast<uint4*>(dh + j) = make_uint4(hw[0], hw[1], hw[2], hw[3]);
            *reinterpret_cast<uint4*>(dl + j) = make_uint4(lw[0], lw[1], lw[2], lw[3]);
        }
    }
}

__global__ void zero_k(float* __restrict__ p, long n)
{
    long i = (long)blockIdx.x * blockDim.x + threadIdx.x;
    if (i < n) p[i] = 0.0f;
}

// fused weight conversion: two fp32 tensors -> bf16 hi/lo pairs in one launch
__global__ __launch_bounds__(256) void convP2_k(
    const float* __restrict__ a, long na, ush* __restrict__ ah, ush* __restrict__ al,
    const float* __restrict__ bb, long nb2, ush* __restrict__ bh, ush* __restrict__ bl)
{
    long i = (long)blockIdx.x * 256 + threadIdx.x;
    if (i < na) {
        ush h, l;
        split2(a[i], h, l);
        ah[i] = h; al[i] = l;
    } else if (i < na + nb2) {
        long j = i - na;
        ush h, l;
        split2(bb[j], h, l);
        bh[j] = h; bl[j] = l;
    }
}

// transpose-convert: in [b][R][Cc] fp32 -> out pairs [b][Cc][R]
__global__ __launch_bounds__(256) void convT_k(const float* __restrict__ in,
    ush* __restrict__ oh, ush* __restrict__ ol, int R, int Cc)
{
    __shared__ float tsm[32][33];
    const int b = blockIdx.z, c0 = blockIdx.x * 32, r0 = blockIdx.y * 32;
    const int lane = threadIdx.x & 31, wy = threadIdx.x >> 5;
    const float* src = in + ((long)b * R + r0) * Cc + c0;
    #pragma unroll
    for (int p = 0; p < 4; p++) {
        int r = wy + p * 8;
        tsm[r][lane] = src[(long)r * Cc + lane];
    }
    __syncthreads();
    ush* dh = oh + ((long)b * Cc + c0) * R + r0;
    ush* dl = ol + ((long)b * Cc + c0) * R + r0;
    #pragma unroll
    for (int p = 0; p < 4; p++) {
        int cc = wy + p * 8;
        float v = tsm[lane][cc];
        ush h, l;
        split2(v, h, l);
        dh[(long)cc * R + lane] = h;
        dl[(long)cc * R + lane] = l;
    }
}

// fused transpose-convert for x (blocks 0..127) and z (blocks 128..129); R = NC
__global__ __launch_bounds__(256) void convTX_k(
    const float* __restrict__ xin, ush* __restrict__ xh, ush* __restrict__ xl,
    const float* __restrict__ zin, ush* __restrict__ zh, ush* __restrict__ zl)
{
    __shared__ float tsm[32][33];
    const int b = blockIdx.z, bx = blockIdx.x;
    const float* in; ush* oh; ush* ol; int Cc, c0;
    if (bx < 128) { in = xin; oh = xh; ol = xl; Cc = NHW; c0 = bx * 32; }
    else          { in = zin; oh = zh; ol = zl; Cc = NK;  c0 = (bx - 128) * 32; }
    const int r0 = blockIdx.y * 32;
    const int lane = threadIdx.x & 31, wy = threadIdx.x >> 5;
    const float* src = in + ((long)b * NC + r0) * Cc + c0;
    #pragma unroll
    for (int p = 0; p < 4; p++) {
        int r = wy + p * 8;
        tsm[r][lane] = src[(long)r * Cc + lane];
    }
    __syncthreads();
    ush* dh = oh + ((long)b * Cc + c0) * NC + r0;
    ush* dl = ol + ((long)b * Cc + c0) * NC + r0;
    #pragma unroll
    for (int p = 0; p < 4; p++) {
        int cc = wy + p * 8;
        float v = tsm[lane][cc];
        ush h, l;
        split2(v, h, l);
        dh[(long)cc * NC + lane] = h;
        dl[(long)cc * NC + lane] = l;
    }
}

// ------------------ depthwise 3x3: division-free staging + row-pair compute ---
__global__ __launch_bounds__(256) void dw_k(
    const float* __restrict__ corr, const float* __restrict__ dten,
    const float* __restrict__ w, const float* __restrict__ bias, float* __restrict__ out)
{
    const int bc = blockIdx.x;
    const int b = bc / NIN, ch = bc % NIN;
    const float* src = (ch < NK) ? (corr + ((long)b * NK + ch) * NHW)
                                 : (dten + ((long)b * NC + (ch - NK)) * NHW);
    __shared__ float tile[66][66];
    const int t = threadIdx.x;
    const int wid = t >> 5, lane = t & 31;

    for (int row = wid; row < 66; row += 8) {
        const int gy = row - 1;
        float* trow = tile[row];
        if (gy >= 0 && gy < 64) {
            const float* srow = src + gy * 64;
            for (int col = lane; col < 66; col += 32) {
                int gx = col - 1;
                trow[col] = (gx >= 0 && gx < 64) ? srow[gx] : 0.0f;
            }
        } else {
            for (int col = lane; col < 66; col += 32) trow[col] = 0.0f;
        }
    }
    __syncthreads();

    float wk[9];
    #pragma unroll
    for (int i = 0; i < 9; i++) wk[i] = w[ch * 9 + i];
    const float bb = bias[ch];

    const int seg = (t & 7) * 8;
    const int tr  = t >> 3;
    const int y   = tr * 2;
    float rv[4][10];
    #pragma unroll
    for (int ky = 0; ky < 4; ky++) {
        const float* trp = &tile[y + ky][seg];
        #pragma unroll
        for (int i = 0; i < 10; i++) rv[ky][i] = trp[i];
    }
    float o0[8], o1[8];
    #pragma unroll
    for (int j = 0; j < 8; j++) {
        float a0 = bb, a1 = bb;
        #pragma unroll
        for (int kx = 0; kx < 3; kx++) {
            a0 = fmaf(wk[0 * 3 + kx], rv[0][j + kx], a0);
            a0 = fmaf(wk[1 * 3 + kx], rv[1][j + kx], a0);
            a0 = fmaf(wk[2 * 3 + kx], rv[2][j + kx], a0);
            a1 = fmaf(wk[0 * 3 + kx], rv[1][j + kx], a1);
            a1 = fmaf(wk[1 * 3 + kx], rv[2][j + kx], a1);
            a1 = fmaf(wk[2 * 3 + kx], rv[3][j + kx], a1);
        }
        o0[j] = a0; o1[j] = a1;
    }
    float* dst = out + (long)bc * NHW + y * 64 + seg;
    *reinterpret_cast<float4*>(dst)          = make_float4(o0[0], o0[1], o0[2], o0[3]);
    *reinterpret_cast<float4*>(dst + 4)      = make_float4(o0[4], o0[5], o0[6], o0[7]);
    *reinterpret_cast<float4*>(dst + 64)     = make_float4(o1[0], o1[1], o1[2], o1[3]);
    *reinterpret_cast<float4*>(dst + 68)     = make_float4(o1[4], o1[5], o1[6], o1[7]);
}

__global__ __launch_bounds__(256) void uw_k(
    const float* __restrict__ Wq, const float* __restrict__ Wk,
    const float* __restrict__ r, float* __restrict__ u, float* __restrict__ w)
{
    int b = blockIdx.x, t = threadIdx.x;
    __shared__ float rs[NC];
    rs[t] = r[b * NC + t];
    __syncthreads();
    float uu = 0.0f, ww = 0.0f;
    for (int c = 0; c < NC; c++) {
        float rc = rs[c];
        uu = fmaf(Wq[t * NC + c], rc, uu);
        ww = fmaf(Wk[t * NC + c], rc, ww);
    }
    u[b * NC + t] = uu;
    w[b * NC + t] = ww;
}

__global__ __launch_bounds__(256) void softmax_k(float* __restrict__ s)
{
    float* p = s + (long)blockIdx.x * NC;
    int t = threadIdx.x, lane = t & 31, wp = t >> 5;
    __shared__ float redm[8], reds[8];
    __shared__ float bm, bs;
    float v = p[t];
    float m = v;
    #pragma unroll
    for (int o = 16; o; o >>= 1) m = fmaxf(m, __shfl_xor_sync(0xffffffffu, m, o));
    if (lane == 0) redm[wp] = m;
    __syncthreads();
    if (t == 0) {
        float mm = redm[0];
        for (int i = 1; i < 8; i++) mm = fmaxf(mm, redm[i]);
        bm = mm;
    }
    __syncthreads();
    float e = expf(v - bm);
    float su = e;
    #pragma unroll
    for (int o = 16; o; o >>= 1) su += __shfl_xor_sync(0xffffffffu, su, o);
    if (lane == 0) reds[wp] = su;
    __syncthreads();
    if (t == 0) {
        float ss = 0.0f;
        for (int i = 0; i < 8; i++) ss += reds[i];
        bs = 1.0f / ss;
    }
    __syncthreads();
    p[t] = e * bs;
}

__global__ __launch_bounds__(256) void ycvec_k(
    const float* __restrict__ att, const float* __restrict__ bv,
    const float* __restrict__ Wo, const float* __restrict__ ob, float* __restrict__ cvec)
{
    int b = blockIdx.x, t = threadIdx.x;
    __shared__ float ys[NC];
    const float* ab = att + (long)b * NC * NC;
    float y = 0.0f;
    for (int c = 0; c < NC; c++) y = fmaf(ab[c * NC + t], bv[c], y);
    ys[t] = y;
    __syncthreads();
    float cv = 0.0f;
    for (int d = 0; d < NC; d++) cv = fmaf(Wo[t * NC + d], ys[d], cv);
    cvec[b * NC + t] = cv + ob[t];
}

// ------------- small scalar GEMM (64x64 tile, 4x4/thread) ---------------------
// EPI: 0 none | 3 score epilogue | 5 plain store + emit bf16 pairs (oh/ol)
template<int AM, int BM, int EPI>
__global__ __launch_bounds__(256) void gemm_k(
    const float* __restrict__ A, const float* __restrict__ Bm, float* __restrict__ Cm,
    int M, int N, int Kd, long aBS, long bBS, long cBS,
    const float* __restrict__ p0, const float* __restrict__ p1,
    const float* __restrict__ p2, const float* __restrict__ p3,
    ush* __restrict__ oh, ush* __restrict__ ol)
{
    __shared__ float As[16][64];
    __shared__ float Bs[16][64];
    const int b = blockIdx.z;
    const float* Ab = A + (long)b * aBS;
    const float* Bb = Bm + (long)b * bBS;
    float* Cb = Cm + (long)b * cBS;
    const int n0 = blockIdx.x * 64, m0 = blockIdx.y * 64;
    const int t = threadIdx.x, tx = t & 15, ty = t >> 4;
    float acc[4][4] = {};
    for (int k0 = 0; k0 < Kd; k0 += 16) {
        if (AM == 0) {
            int m = t >> 2, kq = (t & 3) * 4;
            float4 va = *reinterpret_cast<const float4*>(&Ab[(long)(m0 + m) * Kd + k0 + kq]);
            As[kq + 0][m] = va.x; As[kq + 1][m] = va.y;
            As[kq + 2][m] = va.z; As[kq + 3][m] = va.w;
        } else {
            int kk = t >> 4, mq = (t & 15) * 4;
            float4 va = *reinterpret_cast<const float4*>(&Ab[(long)(k0 + kk) * M + m0 + mq]);
            *reinterpret_cast<float4*>(&As[kk][mq]) = va;
        }
        if (BM == 0) {
            int kk = t >> 4, nq = (t & 15) * 4;
            float4 vb = *reinterpret_cast<const float4*>(&Bb[(long)(k0 + kk) * N + n0 + nq]);
            *reinterpret_cast<float4*>(&Bs[kk][nq]) = vb;
        } else {
            int n = t >> 2, kq = (t & 3) * 4;
            float4 vb = *reinterpret_cast<const float4*>(&Bb[(long)(n0 + n) * Kd + k0 + kq]);
            Bs[kq + 0][n] = vb.x; Bs[kq + 1][n] = vb.y;
            Bs[kq + 2][n] = vb.z; Bs[kq + 3][n] = vb.w;
        }
        __syncthreads();
        #pragma unroll
        for (int kk = 0; kk < 16; kk++) {
            float4 af = *reinterpret_cast<const float4*>(&As[kk][ty * 4]);
            float4 bf = *reinterpret_cast<const float4*>(&Bs[kk][tx * 4]);
            float a[4] = {af.x, af.y, af.z, af.w};
            float bb[4] = {bf.x, bf.y, bf.z, bf.w};
            #pragma unroll
            for (int i = 0; i < 4; i++)
                #pragma unroll
                for (int j = 0; j < 4; j++)
                    acc[i][j] = fmaf(a[i], bb[j], acc[i][j]);
        }
        __syncthreads();
    }
    #pragma unroll
    for (int i = 0; i < 4; i++) {
        int m = m0 + ty * 4 + i;
        float vv[4];
        #pragma unroll
        for (int j = 0; j < 4; j++) {
            int n = n0 + tx * 4 + j;
            float x = acc[i][j];
            if (EPI == 3) {
                float u = p0[b * NC + m], bk = p1[n], bq = p2[m], w = p3[b * NC + n];
                x = (x + u * bk + bq * w + 4096.0f * bq * bk) * 0.0625f;
            }
            vv[j] = x;
        }
        *reinterpret_cast<float4*>(&Cb[(long)m * N + n0 + tx * 4]) =
            make_float4(vv[0], vv[1], vv[2], vv[3]);
        if (EPI == 5) {
            uint32_t hw[2], lw[2];
            #pragma unroll
            for (int p = 0; p < 2; p++) {
                ush h0, l0, h1, l1;
                split2(vv[2 * p], h0, l0);
                split2(vv[2 * p + 1], h1, l1);
                hw[p] = (uint32_t)h0 | ((uint32_t)h1 << 16);
                lw[p] = (uint32_t)l0 | ((uint32_t)l1 << 16);
            }
            *reinterpret_cast<uint2*>(&oh[(long)b * cBS + (long)m * N + n0 + tx * 4]) =
                make_uint2(hw[0], hw[1]);
            *reinterpret_cast<uint2*>(&ol[(long)b * cBS + (long)m * N + n0 + tx * 4]) =
                make_uint2(lw[0], lw[1]);
        }
    }
}

// =============================================================================
extern "C" void kernel_launch(void* const* d_in, const int* in_sizes, int n_in,
                              void* d_out, int out_size)
{
    const float* z     = (const float*)d_in[0];
    const float* x     = (const float*)d_in[1];
    const float* dten  = (const float*)d_in[2];
    const float* dw_w  = (const float*)d_in[3];
    const float* dw_b  = (const float*)d_in[4];
    const float* pw_w  = (const float*)d_in[5];
    const float* pw_b  = (const float*)d_in[6];
    const float* bn_g  = (const float*)d_in[7];
    const float* bn_be = (const float*)d_in[8];
    const float* bn_m  = (const float*)d_in[9];
    const float* bn_v  = (const float*)d_in[10];
    const float* inp_w = (const float*)d_in[11];
    const float* inp_b = (const float*)d_in[12];
    const float* q_w   = (const float*)d_in[13];
    const float* q_b   = (const float*)d_in[14];
    const float* k_w   = (const float*)d_in[15];
    const float* k_b   = (const float*)d_in[16];
    const float* v_w   = (const float*)d_in[17];
    const float* v_b   = (const float*)d_in[18];
    const float* op_w  = (const float*)d_in[19];
    const float* op_b  = (const float*)d_in[20];
    float* out = (float*)d_out;

    float* base = nullptr;
    cudaGetSymbolAddress((void**)&base, g_scratch);
    float* corr = base + OFF_CORR;
    float* dwb  = base + OFF_DW;
    float* sbuf = base + OFF_S;
    float* px   = base + OFF_PX;
    float* G    = base + OFF_G;
    float* T1   = base + OFF_T1;
    float* att  = base + OFF_ATT;
    float* T2   = base + OFF_T2;
    float* Mm   = base + OFF_M;
    float* r    = base + OFF_R;
    float* u    = base + OFF_U;
    float* w    = base + OFF_W2;
    float* cvec = base + OFF_CV;
    ush* ztH  = (ush*)(base + OFF_ZT_H);  ush* ztL  = (ush*)(base + OFF_ZT_L);
    ush* xtH  = (ush*)(base + OFF_XT_H);  ush* xtL  = (ush*)(base + OFF_XT_L);
    ush* dwtH = (ush*)(base + OFF_DWT_H); ush* dwtL = (ush*)(base + OFF_DWT_L);
    ush* stH  = (ush*)(base + OFF_ST_H);  ush* stL  = (ush*)(base + OFF_ST_L);
    ush* pxpH = (ush*)(base + OFF_PXP_H); ush* pxpL = (ush*)(base + OFF_PXP_L);
    ush* pxtH = (ush*)(base + OFF_PXT_H); ush* pxtL = (ush*)(base + OFF_PXT_L);
    ush* pwwH = (ush*)(base + OFF_PWW_H); ush* pwwL = (ush*)(base + OFF_PWW_L);
    ush* inwH = (ush*)(base + OFF_INW_H); ush* inwL = (ush*)(base + OFF_INW_L);
    ush* mmpH = (ush*)(base + OFF_MMP_H); ush* mmpL = (ush*)(base + OFF_MMP_L);

    cudaFuncSetAttribute(mg2_k<0,1>, cudaFuncAttributeMaxDynamicSharedMemorySize, MG2_SMEM);
    cudaFuncSetAttribute(mg2_k<1,1>, cudaFuncAttributeMaxDynamicSharedMemorySize, MG2_SMEM);
    cudaFuncSetAttribute(mg2_k<2,1>, cudaFuncAttributeMaxDynamicSharedMemorySize, MG2_SMEM);
    cudaFuncSetAttribute(mg2_k<4,1>, cudaFuncAttributeMaxDynamicSharedMemorySize, MG2_SMEM);
    cudaFuncSetAttribute(mg2_k<0,4>, cudaFuncAttributeMaxDynamicSharedMemorySize, MG2_SMEM);

    dim3 blk(256);
    const float* np = nullptr;
    ush* nu = nullptr;
    float* nf = nullptr;

    // 1) fused weight conversion (pw_w + inp_w)
    convP2_k<<<(int)(((long)NC*NIN + (long)NC*NC + 255) / 256), blk>>>(
        pw_w, (long)NC*NIN, pwwH, pwwL, inp_w, (long)NC*NC, inwH, inwL);

    // 2) fused transpose-convert (x + z)
    convTX_k<<<dim3(130, 8, NB), blk>>>(x, xtH, xtL, z, ztH, ztL);

    // 3) corr[b] (64x4096) = zT @ xT^T
    mg2_k<0,1><<<dim3(32, 1, NB), blk, MG2_SMEM>>>(
        ztH, ztL, (long)NK*NC, NK, xtH, xtL, (long)NHW*NC,
        corr, (long)NK*NHW, NHW, NC, np,np,np,np,np, nu,nu,nu,nu, 0, nf);

    // 4) depthwise (division-free), 5) transpose-convert its output
    dw_k<<<NB*NIN, blk>>>(corr, dten, dw_w, dw_b, dwb);
    convT_k<<<dim3(128, 10, NB), blk>>>(dwb, dwtH, dwtL, NIN, NHW);

    // 6) s = ReLU(BN(pw_w @ dw + b));  epilogue also emits sT pairs
    mg2_k<2,1><<<dim3(32, 2, NB), blk, MG2_SMEM>>>(
        pwwH, pwwL, 0L, NC, dwtH, dwtL, (long)NHW*NIN,
        sbuf, (long)NC*NHW, NHW, NIN, pw_b, bn_m, bn_v, bn_g, bn_be,
        nu, nu, stH, stL, NC, nf);

    // 7) px GEMM: emits pxP + pxT pairs + fused rowsum into r (zeroed first);
    //    NO fp32 px store (nothing consumes it anymore)
    zero_k<<<(NB*NC + 1023)/1024, 1024>>>(r, (long)NB*NC);
    mg2_k<1,1><<<dim3(32, 2, NB), blk, MG2_SMEM>>>(
        inwH, inwL, 0L, NC, stH, stL, (long)NHW*NC,
        px, (long)NC*NHW, NHW, NC, inp_b, np,np,np,np,
        pxpH, pxpL, pxtH, pxtL, NC, r);

    // 8) G[b] = px @ px^T  (split-K x4, atomicAdd)
    zero_k<<<(int)(((long)NB*NC*NC + 1023)/1024), 1024>>>(G, (long)NB*NC*NC);
    mg2_k<0,4><<<dim3(2, 2, NB*4), blk, MG2_SMEM>>>(
        pxpH, pxpL, (long)NC*NHW, NC, pxpH, pxpL, (long)NC*NHW,
        G, (long)NC*NC, NC, NHW, np,np,np,np,np, nu,nu,nu,nu, 0, nf);

    // 9) small chain (scalar)
    uw_k<<<NB, blk>>>(q_w, k_w, r, u, w);
    gemm_k<0,0,0><<<dim3(4, 4, NB), blk>>>(q_w, G, T1, NC, NC, NC,
        0L, (long)NC*NC, (long)NC*NC, np, np, np, np, nu, nu);
    gemm_k<0,1,3><<<dim3(4, 4, NB), blk>>>(T1, k_w, att, NC, NC, NC,
        (long)NC*NC, 0L, (long)NC*NC, u, k_b, q_b, w, nu, nu);
    softmax_k<<<NB*NC, blk>>>(att);
    ycvec_k<<<NB, blk>>>(att, v_b, op_w, op_b, cvec);
    gemm_k<1,0,0><<<dim3(4, 4, NB), blk>>>(att, v_w, T2, NC, NC, NC,
        (long)NC*NC, 0L, (long)NC*NC, np, np, np, np, nu, nu);
    gemm_k<0,0,5><<<dim3(4, 4, NB), blk>>>(op_w, T2, Mm, NC, NC, NC,
        0L, (long)NC*NC, (long)NC*NC, np, np, np, np, mmpH, mmpL);

    // 10) out = Mm @ px + cvec + s
    mg2_k<4,1><<<dim3(32, 2, NB), blk, MG2_SMEM>>>(
        mmpH, mmpL, (long)NC*NC, NC, pxtH, pxtL, (long)NHW*NC,
        out, (long)NC*NHW, NHW, NC, cvec, sbuf, np,np,np, nu,nu,nu,nu, 0, nf);
}